// round 3
// baseline (speedup 1.0000x reference)
#include <cuda_runtime.h>
#include <math.h>
#include <stdint.h>

#define NNODE 16384
#define DCAT  1024
#define DHEAD 512
#define MAXE  (524288 + NNODE)

// ---------------- scratch (device globals; allocation-free contract) -------
__device__ float  g_xh[NNODE * DCAT];     // x @ W
__device__ float  g_h[NNODE * DCAT];      // aggregated + bias + relu
__device__ float  g_h128[NNODE * 128];
__device__ float  g_h64[NNODE * 64];
__device__ float4 g_hp[NNODE];            // (h3.x, h3.y, h3.z, sq)
__device__ float  g_asrc[NNODE * 2];
__device__ float  g_adst[NNODE * 2];
__device__ float  g_z[NNODE * 2];
__device__ int    g_deg[NNODE];
__device__ int    g_cursor[NNODE];
__device__ int    g_rowptr[NNODE + 1];
__device__ int    g_csr_src[MAXE];
__device__ float2 g_csr_alpha[MAXE];

// ---------------- generic fp32 SGEMM: C = A[M,K] @ B[K,N] (+bias)(+relu) ---
// BM=BN=128, BK=8, 256 threads, 8x8 per thread. MODE selects A/C from device
// globals (compile-time) so kernel_launch never touches symbol addresses:
//   MODE 0: A = Aarg (harness input x), C = g_xh
//   MODE 1: A = g_h,                    C = g_h128
//   MODE 2: A = g_h128,                 C = g_h64
template <int MODE, bool RELU>
__global__ __launch_bounds__(256)
void sgemm128(int M, int N, int K,
              const float* __restrict__ Aarg, const float* __restrict__ B,
              const float* __restrict__ bias)
{
    const float* __restrict__ A =
        (MODE == 0) ? Aarg : (MODE == 1) ? (const float*)g_h : (const float*)g_h128;
    float* __restrict__ C =
        (MODE == 0) ? (float*)g_xh : (MODE == 1) ? (float*)g_h128 : (float*)g_h64;

    constexpr int BM = 128, BN = 128, BK = 8;
    __shared__ float As[BK][BM + 4];
    __shared__ float Bs[BK][BN];

    const int tid  = threadIdx.x;
    const int bx   = blockIdx.x, by = blockIdx.y;
    const int trow = tid / 16;          // 0..15
    const int tcol = tid % 16;          // 0..15
    const int row0 = by * BM + trow * 8;
    const int col0 = bx * BN + tcol * 8;

    const int aRow = tid >> 1;          // 0..127
    const int aK   = (tid & 1) * 4;     // 0 or 4
    const int bK   = tid >> 5;          // 0..7
    const int bCol = (tid & 31) * 4;    // 0..124

    float acc[8][8];
#pragma unroll
    for (int i = 0; i < 8; i++)
#pragma unroll
        for (int j = 0; j < 8; j++) acc[i][j] = 0.f;

    const float* Aptr = A + (size_t)(by * BM + aRow) * K + aK;
    const float* Bptr = B + (size_t)bK * N + bx * BN + bCol;
    const bool bIn = (bx * BN + bCol) < N;

    for (int k0 = 0; k0 < K; k0 += BK) {
        float4 av = *(const float4*)(Aptr + k0);
        As[aK + 0][aRow] = av.x;
        As[aK + 1][aRow] = av.y;
        As[aK + 2][aRow] = av.z;
        As[aK + 3][aRow] = av.w;
        float4 bv = bIn ? *(const float4*)(Bptr + (size_t)k0 * N)
                        : make_float4(0.f, 0.f, 0.f, 0.f);
        *(float4*)&Bs[bK][bCol] = bv;
        __syncthreads();
#pragma unroll
        for (int kk = 0; kk < BK; kk++) {
            float4 a0 = *(const float4*)&As[kk][trow * 8];
            float4 a1 = *(const float4*)&As[kk][trow * 8 + 4];
            float4 b0 = *(const float4*)&Bs[kk][tcol * 8];
            float4 b1 = *(const float4*)&Bs[kk][tcol * 8 + 4];
            float ar[8] = {a0.x, a0.y, a0.z, a0.w, a1.x, a1.y, a1.z, a1.w};
            float br[8] = {b0.x, b0.y, b0.z, b0.w, b1.x, b1.y, b1.z, b1.w};
#pragma unroll
            for (int i = 0; i < 8; i++)
#pragma unroll
                for (int j = 0; j < 8; j++) acc[i][j] += ar[i] * br[j];
        }
        __syncthreads();
    }

#pragma unroll
    for (int j = 0; j < 8; j++) {
        int c = col0 + j;
        if (c >= N) continue;
        float bv = bias ? bias[c] : 0.f;
#pragma unroll
        for (int i = 0; i < 8; i++) {
            float v = acc[i][j] + bv;
            if (RELU) v = fmaxf(v, 0.f);
            C[(size_t)(row0 + i) * N + c] = v;
        }
    }
}

// ---------------- attention scores: a_src/a_dst [N,2] ----------------------
__global__ __launch_bounds__(128)
void attn_scores(const float* __restrict__ att_src,
                 const float* __restrict__ att_dst)
{
    int n = blockIdx.x;
    int w = threadIdx.x >> 5;      // 0..3
    int lane = threadIdx.x & 31;
    int h = w & 1;
    const float* row = g_xh + (size_t)n * DCAT + h * DHEAD;
    const float* att = ((w < 2) ? att_src : att_dst) + h * DHEAD;
    float s = 0.f;
    for (int i = lane; i < DHEAD; i += 32) s += row[i] * att[i];
#pragma unroll
    for (int o = 16; o > 0; o >>= 1) s += __shfl_down_sync(0xffffffffu, s, o);
    if (lane == 0) {
        float* out = (w < 2) ? g_asrc : g_adst;
        out[n * 2 + h] = s;
    }
}

// ---------------- zero init (z, deg) ---------------------------------------
__global__ void zero_init_kernel()
{
    int i = blockIdx.x * blockDim.x + threadIdx.x;
    if (i < NNODE * 2) g_z[i] = 0.f;
    if (i < NNODE) g_deg[i] = 0;
}

__device__ __forceinline__ float leaky(float x) { return x > 0.f ? x : 0.2f * x; }

// edge_index is int32 (JAX default config downcasts jnp.int64 to int32).
// Indices are in [0, NNODE); the &(NNODE-1) mask is a no-op on valid data but
// converts any surprise into a wrong value instead of a device trap.
__device__ __forceinline__ void edge_sd(const int* __restrict__ ei, int e,
                                        int E, int& s, int& d)
{
    if (e < E) {
        s = ei[e] & (NNODE - 1);
        d = ei[E + e] & (NNODE - 1);
    } else {
        s = d = e - E;   // self-loop
    }
}

// ---------------- edge pass 1: softmax denominator + degree ----------------
__global__ __launch_bounds__(256)
void edge_pass1(const int* __restrict__ ei, int E, int Etot)
{
    int e = blockIdx.x * blockDim.x + threadIdx.x;
    if (e >= Etot) return;
    int s, d;
    edge_sd(ei, e, E, s, d);
#pragma unroll
    for (int h = 0; h < 2; h++) {
        float l = leaky(g_asrc[2 * s + h] + g_adst[2 * d + h]);
        atomicAdd(&g_z[2 * d + h], expf(l));
    }
    atomicAdd(&g_deg[d], 1);
}

// ---------------- exclusive scan of degrees --> rowptr, cursor -------------
__global__ __launch_bounds__(512)
void scan_kernel()
{
    __shared__ int sums[512];
    int t = threadIdx.x;
    int base = t * 32;
    int local[32];
    int s = 0;
#pragma unroll
    for (int i = 0; i < 32; i++) { local[i] = s; s += g_deg[base + i]; }
    sums[t] = s;
    __syncthreads();
    for (int off = 1; off < 512; off <<= 1) {
        int v = (t >= off) ? sums[t - off] : 0;
        __syncthreads();
        if (t >= off) sums[t] += v;
        __syncthreads();
    }
    int prefix = (t == 0) ? 0 : sums[t - 1];
#pragma unroll
    for (int i = 0; i < 32; i++) {
        g_rowptr[base + i] = prefix + local[i];
        g_cursor[base + i] = prefix + local[i];
    }
    if (t == 511) g_rowptr[NNODE] = sums[511];
}

// ---------------- edge pass 2: scatter CSR entries (src, alpha) ------------
__global__ __launch_bounds__(256)
void edge_scatter(const int* __restrict__ ei, int E, int Etot)
{
    int e = blockIdx.x * blockDim.x + threadIdx.x;
    if (e >= Etot) return;
    int s, d;
    edge_sd(ei, e, E, s, d);
    int pos = atomicAdd(&g_cursor[d], 1);
    float2 al;
    {
        float l0 = leaky(g_asrc[2 * s + 0] + g_adst[2 * d + 0]);
        float l1 = leaky(g_asrc[2 * s + 1] + g_adst[2 * d + 1]);
        al.x = expf(l0) / fmaxf(g_z[2 * d + 0], 1e-16f);
        al.y = expf(l1) / fmaxf(g_z[2 * d + 1], 1e-16f);
    }
    g_csr_src[pos] = s;
    g_csr_alpha[pos] = al;
}

// ---------------- aggregation (atomic-free) + bias + relu ------------------
__global__ __launch_bounds__(256)
void aggregate_kernel(const float* __restrict__ bias)
{
    int d = blockIdx.x;
    int c = threadIdx.x * 4;             // 0..1020
    bool head1 = (c >= DHEAD);
    int beg = g_rowptr[d], end = g_rowptr[d + 1];
    float4 acc = make_float4(0.f, 0.f, 0.f, 0.f);
    for (int i = beg; i < end; i++) {
        int s = g_csr_src[i];
        float2 al = g_csr_alpha[i];
        float a = head1 ? al.y : al.x;
        float4 v = *(const float4*)(g_xh + (size_t)s * DCAT + c);
        acc.x += a * v.x; acc.y += a * v.y; acc.z += a * v.z; acc.w += a * v.w;
    }
    float4 b = *(const float4*)(bias + c);
    acc.x = fmaxf(acc.x + b.x, 0.f);
    acc.y = fmaxf(acc.y + b.y, 0.f);
    acc.z = fmaxf(acc.z + b.z, 0.f);
    acc.w = fmaxf(acc.w + b.w, 0.f);
    *(float4*)(g_h + (size_t)d * DCAT + c) = acc;
}

// ---------------- head: h3 = h64 @ W2 + b2, plus sq ------------------------
__global__ __launch_bounds__(256)
void head_kernel(const float* __restrict__ W2, const float* __restrict__ b2)
{
    int n = blockIdx.x * blockDim.x + threadIdx.x;
    if (n >= NNODE) return;
    float a0 = b2[0], a1 = b2[1], a2 = b2[2];
    const float* row = g_h64 + (size_t)n * 64;
#pragma unroll 8
    for (int k = 0; k < 64; k++) {
        float v = row[k];
        a0 = fmaf(v, W2[k * 3 + 0], a0);
        a1 = fmaf(v, W2[k * 3 + 1], a1);
        a2 = fmaf(v, W2[k * 3 + 2], a2);
    }
    float sq = fmaf(a2, a2, fmaf(a1, a1, a0 * a0));
    g_hp[n] = make_float4(a0, a1, a2, sq);
}

// ---------------- cdist: out[i][j] = ||h_i - h_j|| -------------------------
__global__ __launch_bounds__(256)
void cdist_kernel(float* __restrict__ out)
{
    int j = blockIdx.x * blockDim.x + threadIdx.x;   // 0..16383
    int i = blockIdx.y;
    float4 hi = g_hp[i];
    float4 hj = g_hp[j];
    // dot computed with the exact fmaf chain used for sq => diagonal is exact 0
    float dot = fmaf(hi.z, hj.z, fmaf(hi.y, hj.y, hi.x * hj.x));
    float d2 = (hi.w + hj.w) - 2.f * dot;
    d2 = fmaxf(d2, 0.f);
    out[(size_t)i * NNODE + j] = (d2 > 0.f) ? sqrtf(d2) : 0.f;
}

// ---------------------------------------------------------------------------
extern "C" void kernel_launch(void* const* d_in, const int* in_sizes, int n_in,
                              void* d_out, int out_size)
{
    const float* x       = (const float*)d_in[0];
    const int*   ei      = (const int*)d_in[1];      // int32 (JAX default)
    const float* W       = (const float*)d_in[2];
    const float* att_src = (const float*)d_in[3];
    const float* att_dst = (const float*)d_in[4];
    const float* bias    = (const float*)d_in[5];
    const float* Wa      = (const float*)d_in[6];
    const float* ba      = (const float*)d_in[7];
    const float* W1      = (const float*)d_in[8];
    const float* b1      = (const float*)d_in[9];
    const float* W2      = (const float*)d_in[10];
    const float* b2      = (const float*)d_in[11];
    float* out = (float*)d_out;

    int E = in_sizes[1] / 2;
    int Etot = E + NNODE;

    // 1) xh = x @ W      [16384,1024] K=512
    sgemm128<0, false><<<dim3(DCAT / 128, NNODE / 128), 256>>>(
        NNODE, DCAT, 512, x, W, nullptr);

    // 2) attention scores
    attn_scores<<<NNODE, 128>>>(att_src, att_dst);

    // 3) zero z/deg
    zero_init_kernel<<<(NNODE * 2 + 255) / 256, 256>>>();

    // 4) softmax denominator + degree histogram
    edge_pass1<<<(Etot + 255) / 256, 256>>>(ei, E, Etot);

    // 5) scan degrees -> rowptr/cursor
    scan_kernel<<<1, 512>>>();

    // 6) scatter CSR (src, alpha)
    edge_scatter<<<(Etot + 255) / 256, 256>>>(ei, E, Etot);

    // 7) aggregate messages (atomic-free) + bias + relu -> h
    aggregate_kernel<<<NNODE, 256>>>(bias);

    // 8) h128 = relu(h @ Wa + ba)   K=1024, N=128
    sgemm128<1, true><<<dim3(1, NNODE / 128), 256>>>(
        NNODE, 128, DCAT, nullptr, Wa, ba);

    // 9) h64 = relu(h128 @ W1 + b1)  K=128, N=64
    sgemm128<2, true><<<dim3(1, NNODE / 128), 256>>>(
        NNODE, 64, 128, nullptr, W1, b1);

    // 10) h3 + sq
    head_kernel<<<NNODE / 256, 256>>>(W2, b2);

    // 11) cdist
    cdist_kernel<<<dim3(NNODE / 256, NNODE), 256>>>(out);

    (void)n_in; (void)out_size;
}

// round 5
// speedup vs baseline: 2.0750x; 2.0750x over previous
#include <cuda_runtime.h>
#include <math.h>
#include <stdint.h>

#define NNODE 16384
#define DCAT  1024
#define DHEAD 512
#define MAXE  (524288 + NNODE)

// ---------------- scratch (device globals; allocation-free contract) -------
__device__ float  g_xh[NNODE * DCAT];     // x @ W
__device__ float  g_h[NNODE * DCAT];      // aggregated + bias + relu
__device__ float  g_h128[NNODE * 128];
__device__ float  g_h64[NNODE * 64];
__device__ float4 g_hp[NNODE];            // (h3.x, h3.y, h3.z, sq)
__device__ float  g_asrc[NNODE * 2];
__device__ float  g_adst[NNODE * 2];
__device__ float  g_z[NNODE * 2];
__device__ int    g_deg[NNODE];
__device__ int    g_cursor[NNODE];
__device__ int    g_rowptr[NNODE + 1];
__device__ int    g_csr_src[MAXE];
__device__ float2 g_csr_alpha[MAXE];

// ---------------- tf32 helpers ---------------------------------------------
__device__ __forceinline__ uint32_t f2tf32(float f)
{
    uint32_t u;
    asm("cvt.rna.tf32.f32 %0, %1;" : "=r"(u) : "f"(f));
    return u;
}

__device__ __forceinline__ void mma_tf32(float& c0, float& c1, float& c2, float& c3,
                                         uint32_t a0, uint32_t a1, uint32_t a2, uint32_t a3,
                                         uint32_t b0, uint32_t b1)
{
    asm volatile(
        "mma.sync.aligned.m16n8k8.row.col.f32.tf32.tf32.f32 "
        "{%0,%1,%2,%3}, {%4,%5,%6,%7}, {%8,%9}, {%0,%1,%2,%3};"
        : "+f"(c0), "+f"(c1), "+f"(c2), "+f"(c3)
        : "r"(a0), "r"(a1), "r"(a2), "r"(a3), "r"(b0), "r"(b1));
}

// ---------------- tf32 tensor-core GEMM: C = A[M,K] @ B[K,N] (+bias)(+relu)
// BM=128, BN=64, BK=16, 256 threads = 8 warps (4 m x 2 n), 32x32 per warp.
// Requires M%128==0, N%64==0, K%16==0 (true for all three uses).
// MODE selects A/C from device globals at compile time:
//   MODE 0: A = Aarg (input x), C = g_xh
//   MODE 1: A = g_h,            C = g_h128
//   MODE 2: A = g_h128,         C = g_h64
template <int MODE, bool RELU>
__global__ __launch_bounds__(256)
void tf32gemm(int M, int N, int K,
              const float* __restrict__ Aarg, const float* __restrict__ B,
              const float* __restrict__ bias)
{
    const float* __restrict__ A =
        (MODE == 0) ? Aarg : (MODE == 1) ? (const float*)g_h : (const float*)g_h128;
    float* __restrict__ C =
        (MODE == 0) ? (float*)g_xh : (MODE == 1) ? (float*)g_h128 : (float*)g_h64;

    constexpr int BM = 128, BN = 64, BK = 16;
    __shared__ float Am[BM][BK + 4];   // m-major, row stride 20 words (conflict-free frag LDS)
    __shared__ float Bs[BK][BN + 8];   // k-major, row stride 72 words (conflict-free frag LDS)

    const int tid   = threadIdx.x;
    const int lane  = tid & 31;
    const int wid   = tid >> 5;
    const int g     = lane >> 2;       // 0..7
    const int tig   = lane & 3;        // 0..3
    const int warpM = wid & 3;         // 0..3  (32 rows each)
    const int warpN = wid >> 2;        // 0..1  (32 cols each)
    const int m0    = blockIdx.y * BM;
    const int n0    = blockIdx.x * BN;

    float c[2][4][4];
#pragma unroll
    for (int mt = 0; mt < 2; mt++)
#pragma unroll
        for (int nt = 0; nt < 4; nt++)
#pragma unroll
            for (int i = 0; i < 4; i++) c[mt][nt][i] = 0.f;

    const int aRow = tid >> 2;         // 0..63
    const int aK   = (tid & 3) * 4;    // 0,4,8,12
    const int bK   = tid >> 4;         // 0..15
    const int bN   = (tid & 15) * 4;   // 0..60

    for (int k0 = 0; k0 < K; k0 += BK) {
        // --- stage A (two 64-row passes), convert to tf32 on store ---
#pragma unroll
        for (int p = 0; p < 2; p++) {
            int r = p * 64 + aRow;
            float4 v = *(const float4*)(A + (size_t)(m0 + r) * K + k0 + aK);
            float4 w;
            w.x = __uint_as_float(f2tf32(v.x));
            w.y = __uint_as_float(f2tf32(v.y));
            w.z = __uint_as_float(f2tf32(v.z));
            w.w = __uint_as_float(f2tf32(v.w));
            *(float4*)&Am[r][aK] = w;
        }
        // --- stage B ---
        {
            float4 v = *(const float4*)(B + (size_t)(k0 + bK) * N + n0 + bN);
            float4 w;
            w.x = __uint_as_float(f2tf32(v.x));
            w.y = __uint_as_float(f2tf32(v.y));
            w.z = __uint_as_float(f2tf32(v.z));
            w.w = __uint_as_float(f2tf32(v.w));
            *(float4*)&Bs[bK][bN] = w;
        }
        __syncthreads();

#pragma unroll
        for (int kk = 0; kk < BK; kk += 8) {
            uint32_t a[2][4];
#pragma unroll
            for (int mt = 0; mt < 2; mt++) {
                int mm = warpM * 32 + mt * 16 + g;
                a[mt][0] = __float_as_uint(Am[mm][kk + tig]);
                a[mt][1] = __float_as_uint(Am[mm + 8][kk + tig]);
                a[mt][2] = __float_as_uint(Am[mm][kk + tig + 4]);
                a[mt][3] = __float_as_uint(Am[mm + 8][kk + tig + 4]);
            }
            uint32_t b[4][2];
#pragma unroll
            for (int nt = 0; nt < 4; nt++) {
                int nn = warpN * 32 + nt * 8 + g;
                b[nt][0] = __float_as_uint(Bs[kk + tig][nn]);
                b[nt][1] = __float_as_uint(Bs[kk + tig + 4][nn]);
            }
#pragma unroll
            for (int mt = 0; mt < 2; mt++)
#pragma unroll
                for (int nt = 0; nt < 4; nt++)
                    mma_tf32(c[mt][nt][0], c[mt][nt][1], c[mt][nt][2], c[mt][nt][3],
                             a[mt][0], a[mt][1], a[mt][2], a[mt][3],
                             b[nt][0], b[nt][1]);
        }
        __syncthreads();
    }

    // --- epilogue: bias + relu + float2 stores ---
#pragma unroll
    for (int mt = 0; mt < 2; mt++) {
        int r0 = m0 + warpM * 32 + mt * 16 + g;
#pragma unroll
        for (int nt = 0; nt < 4; nt++) {
            int cc = n0 + warpN * 32 + nt * 8 + 2 * tig;
            float b0 = 0.f, b1 = 0.f;
            if (bias) { b0 = bias[cc]; b1 = bias[cc + 1]; }
            float v00 = c[mt][nt][0] + b0, v01 = c[mt][nt][1] + b1;
            float v10 = c[mt][nt][2] + b0, v11 = c[mt][nt][3] + b1;
            if (RELU) {
                v00 = fmaxf(v00, 0.f); v01 = fmaxf(v01, 0.f);
                v10 = fmaxf(v10, 0.f); v11 = fmaxf(v11, 0.f);
            }
            *(float2*)&C[(size_t)r0 * N + cc]       = make_float2(v00, v01);
            *(float2*)&C[(size_t)(r0 + 8) * N + cc] = make_float2(v10, v11);
        }
    }
}

// ---------------- attention scores: a_src/a_dst [N,2] ----------------------
__global__ __launch_bounds__(128)
void attn_scores(const float* __restrict__ att_src,
                 const float* __restrict__ att_dst)
{
    int n = blockIdx.x;
    int w = threadIdx.x >> 5;      // 0..3
    int lane = threadIdx.x & 31;
    int h = w & 1;
    const float* row = g_xh + (size_t)n * DCAT + h * DHEAD;
    const float* att = ((w < 2) ? att_src : att_dst) + h * DHEAD;
    float s = 0.f;
    for (int i = lane; i < DHEAD; i += 32) s += row[i] * att[i];
#pragma unroll
    for (int o = 16; o > 0; o >>= 1) s += __shfl_down_sync(0xffffffffu, s, o);
    if (lane == 0) {
        float* out = (w < 2) ? g_asrc : g_adst;
        out[n * 2 + h] = s;
    }
}

// ---------------- zero init (z, deg) ---------------------------------------
__global__ void zero_init_kernel()
{
    int i = blockIdx.x * blockDim.x + threadIdx.x;
    if (i < NNODE * 2) g_z[i] = 0.f;
    if (i < NNODE) g_deg[i] = 0;
}

__device__ __forceinline__ float leaky(float x) { return x > 0.f ? x : 0.2f * x; }

// edge_index is int32; mask is a no-op on valid data but converts surprises
// into wrong values instead of device traps.
__device__ __forceinline__ void edge_sd(const int* __restrict__ ei, int e,
                                        int E, int& s, int& d)
{
    if (e < E) {
        s = ei[e] & (NNODE - 1);
        d = ei[E + e] & (NNODE - 1);
    } else {
        s = d = e - E;   // self-loop
    }
}

// ---------------- edge pass 1: softmax denominator + degree ----------------
__global__ __launch_bounds__(256)
void edge_pass1(const int* __restrict__ ei, int E, int Etot)
{
    int e = blockIdx.x * blockDim.x + threadIdx.x;
    if (e >= Etot) return;
    int s, d;
    edge_sd(ei, e, E, s, d);
#pragma unroll
    for (int h = 0; h < 2; h++) {
        float l = leaky(g_asrc[2 * s + h] + g_adst[2 * d + h]);
        atomicAdd(&g_z[2 * d + h], expf(l));
    }
    atomicAdd(&g_deg[d], 1);
}

// ---------------- exclusive scan of degrees --> rowptr, cursor -------------
__global__ __launch_bounds__(512)
void scan_kernel()
{
    __shared__ int sums[512];
    int t = threadIdx.x;
    int base = t * 32;
    int local[32];
    int s = 0;
#pragma unroll
    for (int i = 0; i < 32; i++) { local[i] = s; s += g_deg[base + i]; }
    sums[t] = s;
    __syncthreads();
    for (int off = 1; off < 512; off <<= 1) {
        int v = (t >= off) ? sums[t - off] : 0;
        __syncthreads();
        if (t >= off) sums[t] += v;
        __syncthreads();
    }
    int prefix = (t == 0) ? 0 : sums[t - 1];
#pragma unroll
    for (int i = 0; i < 32; i++) {
        g_rowptr[base + i] = prefix + local[i];
        g_cursor[base + i] = prefix + local[i];
    }
    if (t == 511) g_rowptr[NNODE] = sums[511];
}

// ---------------- edge pass 2: scatter CSR entries (src, alpha) ------------
__global__ __launch_bounds__(256)
void edge_scatter(const int* __restrict__ ei, int E, int Etot)
{
    int e = blockIdx.x * blockDim.x + threadIdx.x;
    if (e >= Etot) return;
    int s, d;
    edge_sd(ei, e, E, s, d);
    int pos = atomicAdd(&g_cursor[d], 1);
    float2 al;
    {
        float l0 = leaky(g_asrc[2 * s + 0] + g_adst[2 * d + 0]);
        float l1 = leaky(g_asrc[2 * s + 1] + g_adst[2 * d + 1]);
        al.x = expf(l0) / fmaxf(g_z[2 * d + 0], 1e-16f);
        al.y = expf(l1) / fmaxf(g_z[2 * d + 1], 1e-16f);
    }
    g_csr_src[pos] = s;
    g_csr_alpha[pos] = al;
}

// ---------------- aggregation (atomic-free) + bias + relu ------------------
__global__ __launch_bounds__(256)
void aggregate_kernel(const float* __restrict__ bias)
{
    int d = blockIdx.x;
    int c = threadIdx.x * 4;             // 0..1020
    bool head1 = (c >= DHEAD);
    int beg = g_rowptr[d], end = g_rowptr[d + 1];
    float4 acc = make_float4(0.f, 0.f, 0.f, 0.f);
    for (int i = beg; i < end; i++) {
        int s = g_csr_src[i];
        float2 al = g_csr_alpha[i];
        float a = head1 ? al.y : al.x;
        float4 v = *(const float4*)(g_xh + (size_t)s * DCAT + c);
        acc.x += a * v.x; acc.y += a * v.y; acc.z += a * v.z; acc.w += a * v.w;
    }
    float4 b = *(const float4*)(bias + c);
    acc.x = fmaxf(acc.x + b.x, 0.f);
    acc.y = fmaxf(acc.y + b.y, 0.f);
    acc.z = fmaxf(acc.z + b.z, 0.f);
    acc.w = fmaxf(acc.w + b.w, 0.f);
    *(float4*)(g_h + (size_t)d * DCAT + c) = acc;
}

// ---------------- head: h3 = h64 @ W2 + b2, plus sq ------------------------
__global__ __launch_bounds__(256)
void head_kernel(const float* __restrict__ W2, const float* __restrict__ b2)
{
    int n = blockIdx.x * blockDim.x + threadIdx.x;
    if (n >= NNODE) return;
    float a0 = b2[0], a1 = b2[1], a2 = b2[2];
    const float* row = g_h64 + (size_t)n * 64;
#pragma unroll 8
    for (int k = 0; k < 64; k++) {
        float v = row[k];
        a0 = fmaf(v, W2[k * 3 + 0], a0);
        a1 = fmaf(v, W2[k * 3 + 1], a1);
        a2 = fmaf(v, W2[k * 3 + 2], a2);
    }
    float sq = fmaf(a2, a2, fmaf(a1, a1, a0 * a0));
    g_hp[n] = make_float4(a0, a1, a2, sq);
}

// ---------------- cdist: out[i][j] = ||h_i - h_j||, 4 j per thread ---------
__global__ __launch_bounds__(256)
void cdist_kernel(float* __restrict__ out)
{
    int j = (blockIdx.x * 256 + threadIdx.x) * 4;    // 0..16380
    int i = blockIdx.y;
    float4 hi = g_hp[i];
    float4 r;
    // dot uses the exact fmaf chain used for sq => diagonal is exactly 0
    {
        float4 hj = g_hp[j + 0];
        float dot = fmaf(hi.z, hj.z, fmaf(hi.y, hj.y, hi.x * hj.x));
        float d2 = fmaxf((hi.w + hj.w) - 2.f * dot, 0.f);
        r.x = (d2 > 0.f) ? sqrtf(d2) : 0.f;
    }
    {
        float4 hj = g_hp[j + 1];
        float dot = fmaf(hi.z, hj.z, fmaf(hi.y, hj.y, hi.x * hj.x));
        float d2 = fmaxf((hi.w + hj.w) - 2.f * dot, 0.f);
        r.y = (d2 > 0.f) ? sqrtf(d2) : 0.f;
    }
    {
        float4 hj = g_hp[j + 2];
        float dot = fmaf(hi.z, hj.z, fmaf(hi.y, hj.y, hi.x * hj.x));
        float d2 = fmaxf((hi.w + hj.w) - 2.f * dot, 0.f);
        r.z = (d2 > 0.f) ? sqrtf(d2) : 0.f;
    }
    {
        float4 hj = g_hp[j + 3];
        float dot = fmaf(hi.z, hj.z, fmaf(hi.y, hj.y, hi.x * hj.x));
        float d2 = fmaxf((hi.w + hj.w) - 2.f * dot, 0.f);
        r.w = (d2 > 0.f) ? sqrtf(d2) : 0.f;
    }
    *(float4*)&out[(size_t)i * NNODE + j] = r;
}

// ---------------------------------------------------------------------------
extern "C" void kernel_launch(void* const* d_in, const int* in_sizes, int n_in,
                              void* d_out, int out_size)
{
    const float* x       = (const float*)d_in[0];
    const int*   ei      = (const int*)d_in[1];      // int32 (JAX default)
    const float* W       = (const float*)d_in[2];
    const float* att_src = (const float*)d_in[3];
    const float* att_dst = (const float*)d_in[4];
    const float* bias    = (const float*)d_in[5];
    const float* Wa      = (const float*)d_in[6];
    const float* ba      = (const float*)d_in[7];
    const float* W1      = (const float*)d_in[8];
    const float* b1      = (const float*)d_in[9];
    const float* W2      = (const float*)d_in[10];
    const float* b2      = (const float*)d_in[11];
    float* out = (float*)d_out;

    int E = in_sizes[1] / 2;
    int Etot = E + NNODE;

    // 1) xh = x @ W   [16384,1024] K=512  (tensor cores, tf32)
    tf32gemm<0, false><<<dim3(DCAT / 64, NNODE / 128), 256>>>(
        NNODE, DCAT, 512, x, W, nullptr);

    // 2) attention scores
    attn_scores<<<NNODE, 128>>>(att_src, att_dst);

    // 3) zero z/deg
    zero_init_kernel<<<(NNODE * 2 + 255) / 256, 256>>>();

    // 4) softmax denominator + degree histogram
    edge_pass1<<<(Etot + 255) / 256, 256>>>(ei, E, Etot);

    // 5) scan degrees -> rowptr/cursor
    scan_kernel<<<1, 512>>>();

    // 6) scatter CSR (src, alpha)
    edge_scatter<<<(Etot + 255) / 256, 256>>>(ei, E, Etot);

    // 7) aggregate messages (atomic-free) + bias + relu -> h
    aggregate_kernel<<<NNODE, 256>>>(bias);

    // 8) h128 = relu(h @ Wa + ba)   K=1024, N=128
    tf32gemm<1, true><<<dim3(2, NNODE / 128), 256>>>(
        NNODE, 128, DCAT, nullptr, Wa, ba);

    // 9) h64 = relu(h128 @ W1 + b1)  K=128, N=64
    tf32gemm<2, true><<<dim3(1, NNODE / 128), 256>>>(
        NNODE, 64, 128, nullptr, W1, b1);

    // 10) h3 + sq
    head_kernel<<<NNODE / 256, 256>>>(W2, b2);

    // 11) cdist (float4 stores)
    cdist_kernel<<<dim3(NNODE / 1024, NNODE), 256>>>(out);

    (void)n_in; (void)out_size;
}